// round 1
// baseline (speedup 1.0000x reference)
#include <cuda_runtime.h>

// heightfield: [16, 1, 512, 512] float32  -> output same shape.
// For each row of 512: out[w] = 1 - clip( max_{r=1..16}( pad(row)[w+r] - r/10 ) - row[w], 0, 1 )
// pad is 16 elements of -1000 appended on the right.

#define IM 512
#define RADIUS 16
#define PAD_VAL (-1000.0f)
#define THREADS 128   // 128 threads * float4 = 512 elements per row

__global__ void shadow_kernel(const float* __restrict__ in, float* __restrict__ out) {
    __shared__ float s[IM + RADIUS];

    const int row = blockIdx.x;            // 16*512 = 8192 rows
    const float* rp = in + (size_t)row * IM;
    float* op = out + (size_t)row * IM;

    const int t = threadIdx.x;

    // Vectorized row load into shared
    reinterpret_cast<float4*>(s)[t] = reinterpret_cast<const float4*>(rp)[t];
    if (t < RADIUS) s[IM + t] = PAD_VAL;
    __syncthreads();

    const int w0 = t * 4;
    float4 h = *reinterpret_cast<const float4*>(&s[w0]);
    float hv[4] = {h.x, h.y, h.z, h.w};
    float res[4];

    #pragma unroll
    for (int j = 0; j < 4; ++j) {
        const int w = w0 + j;
        float m = -1e30f;
        #pragma unroll
        for (int r = 1; r <= RADIUS; ++r) {
            m = fmaxf(m, s[w + r] - (float)r * 0.1f);
        }
        float d = m - hv[j];
        d = fminf(fmaxf(d, 0.0f), 1.0f);
        res[j] = 1.0f - d;
    }

    float4 o = make_float4(res[0], res[1], res[2], res[3]);
    reinterpret_cast<float4*>(op)[t] = o;
}

extern "C" void kernel_launch(void* const* d_in, const int* in_sizes, int n_in,
                              void* d_out, int out_size) {
    const float* in = (const float*)d_in[0];
    float* out = (float*)d_out;
    const int rows = in_sizes[0] / IM;     // 16*1*512 = 8192
    shadow_kernel<<<rows, THREADS>>>(in, out);
}